// round 9
// baseline (speedup 1.0000x reference)
#include <cuda_runtime.h>

// Problem constants (fixed by the reference)
#define Nn    1000
#define INF_  32
#define Hh    128
#define Mm    128
#define DEGk  16
#define Pp    2
#define OUTn  10
#define MAXD  (10 * Nn)                 // dequeue budget = queue slots ever read
#define NSMAX 64
#define MAXMSG (NSMAX + MAXD)           // distinct messages ever created
#define THR   (1.0f - 1e-7f)

// Persistent device state (static allocation — no cudaMalloc allowed)
__device__ float g_feats[Nn * Hh];
__device__ float g_final[Nn * Hh];
__device__ float g_actf[Nn];
__device__ float g_msgs[(size_t)MAXMSG * Mm];   // dedup'd message store (~5.2 MB)

// ---- packed f32x2 helpers (sm_103a) ---------------------------------------
__device__ __forceinline__ unsigned long long fma2(unsigned long long a,
                                                   unsigned long long b,
                                                   unsigned long long c)
{
    unsigned long long d;
    asm("fma.rn.f32x2 %0, %1, %2, %3;" : "=l"(d) : "l"(a), "l"(b), "l"(c));
    return d;
}
__device__ __forceinline__ unsigned long long pack2(float lo, float hi)
{
    unsigned long long d;
    asm("mov.b64 %0, {%1, %2};" : "=l"(d) : "f"(lo), "f"(hi));
    return d;
}
__device__ __forceinline__ void unpack2(unsigned long long v, float& lo, float& hi)
{
    asm("mov.b64 {%0, %1}, %2;" : "=f"(lo), "=f"(hi) : "l"(v));
}

// ---------------------------------------------------------------------------
// Kernel 1: encoder + state init + seed messages + actf seed. grid = Nn x 128
// ---------------------------------------------------------------------------
__global__ void k_init(const float* __restrict__ xa,
                       const float* __restrict__ fmsg,
                       const int*  nstart_p,
                       const float* __restrict__ enc_w,
                       const float* __restrict__ enc_b,
                       const float* __restrict__ act_w)
{
    int n = blockIdx.x, t = threadIdx.x;
    int lane = t & 31;
    __shared__ float sx[INF_];
    __shared__ float sw[4];
    if (t < INF_) sx[t] = xa[n * INF_ + t];
    __syncthreads();

    float acc = enc_b[t];
#pragma unroll
    for (int k = 0; k < INF_; k++) acc += sx[k] * enc_w[k * Hh + t];

    g_feats[n * Hh + t] = acc;
    g_final[n * Hh + t] = 0.0f;

    float pa = acc * act_w[t];
#pragma unroll
    for (int o = 16; o; o >>= 1) pa += __shfl_xor_sync(0xffffffffu, pa, o);
    if (lane == 0) sw[t >> 5] = pa;
    __syncthreads();
    if (t == 0) g_actf[n] = sw[0] + sw[1] + sw[2] + sw[3];

    int ns = nstart_p ? *nstart_p : NSMAX;
    if (n < ns) g_msgs[(size_t)n * Mm + t] = fmsg[n * Mm + t];
}

// ---------------------------------------------------------------------------
// Kernel 2: sequential queue simulation. ONE block, 512 threads (16 warps).
//  Batched steps: up to 4 consecutive processable same-mid distinct-node
//  queue entries are EXACTLY commutable (disjoint node state, shared msg
//  partials, enqueue order preserved) -> one scan/gate/prefetch/matmul pass
//  amortizes all fixed overhead over B<=4 messages.
//  * queue + tact + actf caches in SMEM; msg-half weights in SMEM
//  * hit-path weights register-resident (fma.rn.f32x2), 4 interleaved chains
//  * s_wtmp double-buffered (parity); lazy actf commit with in-register subst
// ---------------------------------------------------------------------------
__global__ void __launch_bounds__(512, 1) k_main(
    const int*  __restrict__ neighbors,
    const int*  nstart_p,
    const float* __restrict__ ns_w, const float* __restrict__ ns_b,
    const float* __restrict__ nm_w, const float* __restrict__ nm_b,
    const float* __restrict__ act_w, const float* __restrict__ act_b)
{
    extern __shared__ __align__(16) float dyn[];
    float* s_mwA  = dyn;                      // ns_w rows 128..255 (64 KB)
    float* s_mwB  = dyn + 128 * 128;          // nm_w rows 128..255 (64 KB)
    int*   s_qpack = (int*)(dyn + 2 * 128 * 128);   // packed queue (40 KB)

    __shared__ float s_tact[Nn];                    // 4 KB
    __shared__ float s_actf[Nn];                    // 4 KB
    __shared__ __align__(16) float xs[4][128];      // feats rows (batch)
    __shared__ __align__(16) float ys[4][128];      // ns outputs (batch)
    __shared__ __align__(16) float s_fin[4][128];   // final rows (batch)
    __shared__ float s_msg[128];
    __shared__ float s_nsmsg[128], s_nmmsg[128];    // cached msg-half partials
    __shared__ __align__(16) float sredA[8 * 128];
    __shared__ __align__(16) float sredB[8 * 128];
    __shared__ float s_actw[256];
    __shared__ float s_nsb[128], s_nmb[128];
    __shared__ __align__(16) float s_wtmp[2][4][16];  // actf partials, dbl-buffered
    __shared__ float s_wactm[4];
    __shared__ float s_actmsg;

    const int t    = threadIdx.x;
    const int lane = t & 31;
    const int warp = t >> 5;
    const unsigned FULL = 0xffffffffu;

    if (t < 256) s_actw[t] = act_w[t];
    if (t < 128) { s_nsb[t] = ns_b[t]; s_nmb[t] = nm_b[t]; }
    if (t < 128) ((float*)s_wtmp)[t] = 0.0f;
    if (t == 0)  s_actmsg = 0.0f;
    const float actb = act_b[0];

    for (int i = t; i < Nn; i += 512) { s_tact[i] = 0.0f; s_actf[i] = g_actf[i]; }

    const int ns0 = nstart_p ? *nstart_p : NSMAX;
    for (int i = t; i < ns0; i += 512) s_qpack[i] = (i << 10) | i;  // mid=i,node=i

    // msg-half weights into SMEM (rows 128..255 of both matrices)
    {
        const float4* a4 = (const float4*)(ns_w + 128 * Hh);
        const float4* b4 = (const float4*)(nm_w + 128 * Hh);
        for (int i = t; i < 128 * 32; i += 512) {
            ((float4*)s_mwA)[i] = a4[i];
            ((float4*)s_mwB)[i] = b4[i];
        }
    }

    // hit-path weights into registers (k-pair packed)
    const int o = (warp << 3) + (lane & 7);     // output column owned
    const int c = lane >> 3;                    // k-chunk (0..3)
    unsigned long long wA[16], wB[16];
#pragma unroll
    for (int kk = 0; kk < 16; kk++) {
        int k = c * 32 + 2 * kk;
        wA[kk] = pack2(ns_w[k * Hh + o], ns_w[(k + 1) * Hh + o]);
        wB[kk] = pack2(nm_w[k * Hh + o], nm_w[(k + 1) * Hh + o]);
    }

    int head = 0, tail = ns0, nproc = 0, last_mid = -1;
    int Bp = 0;                                     // prev batch size
    int pn0 = 0, pn1 = 0, pn2 = 0, pn3 = 0;         // prev batch nodes
    int pp = 0;                                     // s_wtmp read-parity
    __syncthreads();

    while (true) {
        const int limit = (tail < MAXD) ? tail : MAXD;
        if (head >= limit) break;

        // ---- scan + batch build (all warps redundantly, uniform) ----
        int alive = 0, bsz = 0, bmid = -1, lastpos = 0;
        int b0n = 0, b1n = 0, b2n = 0, b3n = 0;
        float b0t = 0.f, b1t = 0.f, b2t = 0.f, b3t = 0.f;
        {
            int p = head;
            while (true) {
                int q = p + lane;
                bool valid = q < limit;
                int pk = valid ? s_qpack[q] : 0;
                int nd = pk & 1023;
                float tv = valid ? s_tact[nd] : 2.0f;
                unsigned rem = __ballot_sync(FULL, valid && (tv <= THR));
                if (rem) {
                    int f = __ffs((int)rem) - 1; rem &= rem - 1;
                    b0n  = __shfl_sync(FULL, nd, f);
                    bmid = __shfl_sync(FULL, pk, f) >> 10;
                    b0t  = __shfl_sync(FULL, tv, f);
                    lastpos = p + f; bsz = 1; alive = 1;
                    while (rem && bsz < 4) {
                        f = __ffs((int)rem) - 1; rem &= rem - 1;
                        int   fn  = __shfl_sync(FULL, nd, f);
                        int   fm  = __shfl_sync(FULL, pk, f) >> 10;
                        float ftv = __shfl_sync(FULL, tv, f);
                        if (fm != bmid) break;
                        bool dup = (fn == b0n) || (bsz > 1 && fn == b1n)
                                               || (bsz > 2 && fn == b2n);
                        if (dup) break;
                        if      (bsz == 1) { b1n = fn; b1t = ftv; }
                        else if (bsz == 2) { b2n = fn; b2t = ftv; }
                        else               { b3n = fn; b3t = ftv; }
                        lastpos = p + f; bsz++;
                    }
                    break;
                }
                if (__ballot_sync(FULL, valid) != FULL) break;  // exhausted
                p += 32;
            }
        }
        if (!alive) break;            // all remaining dequeues are no-ops

        const int   bn[4] = { b0n, b1n, b2n, b3n };
        const float bt[4] = { b0t, b1t, b2t, b3t };
        const int   pn[4] = { pn0, pn1, pn2, pn3 };

        // ---- miss path: msg-half partials for this mid ----
        if (bmid != last_mid) {
            float mv = 0.0f;
            if (t < 128) {
                mv = g_msgs[(size_t)bmid * Mm + t];
                s_msg[t] = mv;
            }
            if (warp < 4) {
                float pa = mv * s_actw[128 + t];
#pragma unroll
                for (int oo = 16; oo; oo >>= 1)
                    pa += __shfl_xor_sync(FULL, pa, oo);
                if (lane == 0) s_wactm[warp] = pa;
            }
            __syncthreads();
            {
                const float4* w4p = (warp < 8) ? (const float4*)s_mwA
                                               : (const float4*)s_mwB;
                float* red = (warp < 8) ? sredA : sredB;
                int wl = warp & 7, kb = (warp & 7) * 16;
                float4 a = make_float4(0.f, 0.f, 0.f, 0.f);
#pragma unroll 8
                for (int kk = 0; kk < 16; kk++) {
                    float  mk = s_msg[kb + kk];
                    float4 w4 = w4p[(kb + kk) * 32 + lane];
                    a.x += mk * w4.x; a.y += mk * w4.y;
                    a.z += mk * w4.z; a.w += mk * w4.w;
                }
                ((float4*)red)[wl * 32 + lane] = a;
            }
            __syncthreads();
            if (t < 128) {
                float sa = 0.f, sb = 0.f;
#pragma unroll
                for (int j = 0; j < 8; j++) {
                    sa += sredA[j * 128 + t];
                    sb += sredB[j * 128 + t];
                }
                s_nsmsg[t] = sa; s_nmmsg[t] = sb;
            }
            if (t == 0)
                s_actmsg = s_wactm[0] + s_wactm[1] + s_wactm[2] + s_wactm[3];
            __syncthreads();
            last_mid = bmid;
        }

        // ---- gate (all threads redundantly) ----
        float ws[4];
        {
            const float4* w4 = (const float4*)&s_wtmp[pp][0][0];
#pragma unroll
            for (int r = 0; r < 4; r++) {
                float4 a = w4[r * 4 + 0], b = w4[r * 4 + 1];
                float4 cc = w4[r * 4 + 2], d = w4[r * 4 + 3];
                ws[r] = ((a.x + a.y) + (a.z + a.w)) + ((b.x + b.y) + (b.z + b.w))
                      + ((cc.x + cc.y) + (cc.z + cc.w)) + ((d.x + d.y) + (d.z + d.w));
            }
        }
#pragma unroll
        for (int r = 0; r < 4; r++)               // commit prev-batch actf
            if (t == r && r < Bp) s_actf[pn[r]] = ws[r];

        float na_[4];
#pragma unroll
        for (int j = 0; j < 4; j++) {
            float af = s_actf[bn[j]];
#pragma unroll
            for (int r = 0; r < 4; r++)
                if (r < Bp && bn[j] == pn[r]) af = ws[r];   // fresh value
            float a = af + s_actmsg + actb;
            float cand = 1.0f / (1.0f + expf(-a));
            float taj = bt[j];
            na_[j] = (taj + cand > 1.0f) ? (1.0f - taj) : cand;
        }
#pragma unroll
        for (int j = 0; j < 4; j++)
            if (t == j && j < bsz) s_tact[bn[j]] = bt[j] + na_[j];

        // ---- prefetch rows + neighbors ----
        int mynb = 0;
        if (t < 128) {
#pragma unroll
            for (int j = 0; j < 4; j++)
                if (j < bsz) {
                    xs[j][t]    = g_feats[bn[j] * Hh + t];
                    s_fin[j][t] = g_final[bn[j] * Hh + t];
                }
        } else if (warp >= 4 && warp < 8) {
            int j = warp - 4;
            if (j < bsz && lane < DEGk)
                mynb = neighbors[bn[j] * DEGk + lane];
        }
        __syncthreads();   // sync1: xs/s_fin/tact/actf visible

        // ---- phase 2: ns matmul (register weights, 4 interleaved rows) ----
        {
            unsigned long long a0[4] = {0ull,0ull,0ull,0ull};
            unsigned long long a1[4] = {0ull,0ull,0ull,0ull};
#pragma unroll
            for (int kk = 0; kk < 8; kk++) {
#pragma unroll
                for (int j = 0; j < 4; j++) {
                    const ulonglong2 xv =
                        ((const ulonglong2*)xs[j])[c * 8 + kk];
                    a0[j] = fma2(xv.x, wA[2 * kk],     a0[j]);
                    a1[j] = fma2(xv.y, wA[2 * kk + 1], a1[j]);
                }
            }
            float rx[4], ry[4];
#pragma unroll
            for (int j = 0; j < 4; j++) {
                float ax, ay, bx, by;
                unpack2(a0[j], ax, ay); unpack2(a1[j], bx, by);
                rx[j] = ax + bx; ry[j] = ay + by;
            }
#pragma unroll
            for (int j = 0; j < 4; j++) {
                rx[j] += __shfl_xor_sync(FULL, rx[j], 8);
                ry[j] += __shfl_xor_sync(FULL, ry[j], 8);
                rx[j] += __shfl_xor_sync(FULL, rx[j], 16);
                ry[j] += __shfl_xor_sync(FULL, ry[j], 16);
            }
            if (c == 0) {
#pragma unroll
                for (int j = 0; j < 4; j++) {
                    float s = rx[j] + ry[j] + s_nsb[o] + s_nsmsg[o];
                    float nsv = fmaxf(s, 0.0f);
                    ys[j][o] = nsv;
                    if (j < bsz) {
                        g_feats[bn[j] * Hh + o] = nsv;
                        g_final[bn[j] * Hh + o] = s_fin[j][o] + nsv * na_[j];
                    }
                    float pw = nsv * s_actw[o];
                    pw += __shfl_xor_sync(0x000000ffu, pw, 4);
                    pw += __shfl_xor_sync(0x000000ffu, pw, 2);
                    pw += __shfl_xor_sync(0x000000ffu, pw, 1);
                    if (lane == 0) s_wtmp[pp ^ 1][j][warp] = pw;
                }
            }
        }
        __syncthreads();   // sync2: ys ready

        // ---- phase 3: nm matmul + msg stores + enqueue ----
        {
            unsigned long long a0[4] = {0ull,0ull,0ull,0ull};
            unsigned long long a1[4] = {0ull,0ull,0ull,0ull};
#pragma unroll
            for (int kk = 0; kk < 8; kk++) {
#pragma unroll
                for (int j = 0; j < 4; j++) {
                    const ulonglong2 yv =
                        ((const ulonglong2*)ys[j])[c * 8 + kk];
                    a0[j] = fma2(yv.x, wB[2 * kk],     a0[j]);
                    a1[j] = fma2(yv.y, wB[2 * kk + 1], a1[j]);
                }
            }
            float rx[4], ry[4];
#pragma unroll
            for (int j = 0; j < 4; j++) {
                float ax, ay, bx, by;
                unpack2(a0[j], ax, ay); unpack2(a1[j], bx, by);
                rx[j] = ax + bx; ry[j] = ay + by;
            }
#pragma unroll
            for (int j = 0; j < 4; j++) {
                rx[j] += __shfl_xor_sync(FULL, rx[j], 8);
                ry[j] += __shfl_xor_sync(FULL, ry[j], 8);
                rx[j] += __shfl_xor_sync(FULL, rx[j], 16);
                ry[j] += __shfl_xor_sync(FULL, ry[j], 16);
            }
            if (c == 0) {
#pragma unroll
                for (int j = 0; j < 4; j++) {
                    if (j < bsz) {
                        float s = rx[j] + ry[j] + s_nmb[o] + s_nmmsg[o];
                        g_msgs[(size_t)(NSMAX + nproc + j) * Mm + o] = s;
                    }
                }
            }
        }
        if (warp >= 4 && warp < 8) {                   // enqueue 16 per row
            int j = warp - 4;
            if (j < bsz && lane < DEGk) {
                int slot = tail + j * DEGk + lane;
                if (slot < MAXD)
                    s_qpack[slot] = ((NSMAX + nproc + j) << 10) | mynb;
            }
        }

        // ---- commit batch state ----
        pn0 = b0n; pn1 = b1n; pn2 = b2n; pn3 = b3n;
        Bp = bsz;
        head = lastpos + 1;
        tail += DEGk * bsz;
        nproc += bsz;
        pp ^= 1;
        __syncthreads();   // sync3: queue/msgs visible for next scan
    }
}

// ---------------------------------------------------------------------------
// Kernel 3: readout.  g = sum_n final; logits = g . dec_w + dec_b; log_softmax
// ---------------------------------------------------------------------------
__global__ void k_readout(const float* __restrict__ dec_w,
                          const float* __restrict__ dec_b,
                          float* __restrict__ out)
{
    __shared__ float sg[Hh];
    __shared__ float sl[Pp * OUTn];
    int t = threadIdx.x;

    float acc = 0.0f;
#pragma unroll 4
    for (int n = 0; n < Nn; n++) acc += g_final[n * Hh + t];
    sg[t] = acc;
    __syncthreads();

    if (t < Pp * OUTn) {
        int p = t / OUTn, o = t - p * OUTn;
        float a = dec_b[t];
#pragma unroll 4
        for (int h = 0; h < Hh; h++)
            a += sg[h] * dec_w[(p * Hh + h) * OUTn + o];
        sl[t] = a;
    }
    __syncthreads();

    if (t < Pp) {
        float mx = -1e30f;
        for (int o = 0; o < OUTn; o++) mx = fmaxf(mx, sl[t * OUTn + o]);
        float s = 0.0f;
        for (int o = 0; o < OUTn; o++) s += expf(sl[t * OUTn + o] - mx);
        float lse = mx + logf(s);
        for (int o = 0; o < OUTn; o++)
            out[t * OUTn + o] = sl[t * OUTn + o] - lse;
    }
}

// ---------------------------------------------------------------------------
extern "C" void kernel_launch(void* const* d_in, const int* in_sizes, int n_in,
                              void* d_out, int out_size)
{
    int off = (n_in >= 14) ? 1 : 0;
    const float* xa        = (const float*)d_in[0];
    const float* fmsg      = (const float*)d_in[1];
    const int*   neighbors = (const int*)  d_in[2];
    const int*   nstart    = off ? (const int*)d_in[3] : nullptr;
    const float* enc_w = (const float*)d_in[3 + off];
    const float* enc_b = (const float*)d_in[4 + off];
    const float* ns_w  = (const float*)d_in[5 + off];
    const float* ns_b  = (const float*)d_in[6 + off];
    const float* nm_w  = (const float*)d_in[7 + off];
    const float* nm_b  = (const float*)d_in[8 + off];
    const float* act_w = (const float*)d_in[9 + off];
    const float* act_b = (const float*)d_in[10 + off];
    const float* dec_w = (const float*)d_in[11 + off];
    const float* dec_b = (const float*)d_in[12 + off];

    // dyn smem: 128 KB msg-half weights + 40 KB packed queue
    static const size_t DYN = 2 * 128 * 128 * sizeof(float) + MAXD * sizeof(int);
    cudaFuncSetAttribute(k_main, cudaFuncAttributeMaxDynamicSharedMemorySize,
                         (int)DYN);

    k_init<<<Nn, Hh>>>(xa, fmsg, nstart, enc_w, enc_b, act_w);
    k_main<<<1, 512, DYN>>>(neighbors, nstart, ns_w, ns_b, nm_w, nm_b,
                            act_w, act_b);
    k_readout<<<1, Hh>>>(dec_w, dec_b, (float*)d_out);
}

// round 14
// speedup vs baseline: 1.0034x; 1.0034x over previous
#include <cuda_runtime.h>

// Problem constants (fixed by the reference)
#define Nn    1000
#define INF_  32
#define Hh    128
#define Mm    128
#define DEGk  16
#define Pp    2
#define OUTn  10
#define MAXD  (10 * Nn)                 // dequeue budget = queue slots ever read
#define NSMAX 64
#define MAXMSG (NSMAX + MAXD)           // distinct messages ever created
#define THR   (1.0f - 1e-7f)

// Persistent device state (static allocation — no cudaMalloc allowed)
__device__ float g_feats[Nn * Hh];
__device__ float g_final[Nn * Hh];
__device__ float g_actf[Nn];
__device__ float g_msgs[(size_t)MAXMSG * Mm];   // dedup'd message store (~5.2 MB)

// ---- packed f32x2 helpers (sm_103a) ---------------------------------------
__device__ __forceinline__ unsigned long long fma2(unsigned long long a,
                                                   unsigned long long b,
                                                   unsigned long long c)
{
    unsigned long long d;
    asm("fma.rn.f32x2 %0, %1, %2, %3;" : "=l"(d) : "l"(a), "l"(b), "l"(c));
    return d;
}
__device__ __forceinline__ unsigned long long pack2(float lo, float hi)
{
    unsigned long long d;
    asm("mov.b64 %0, {%1, %2};" : "=l"(d) : "f"(lo), "f"(hi));
    return d;
}
__device__ __forceinline__ void unpack2(unsigned long long v, float& lo, float& hi)
{
    asm("mov.b64 {%0, %1}, %2;" : "=f"(lo), "=f"(hi) : "l"(v));
}

// ---------------------------------------------------------------------------
// Kernel 1: encoder + state init + seed messages + actf seed. grid = Nn x 128
// ---------------------------------------------------------------------------
__global__ void k_init(const float* __restrict__ xa,
                       const float* __restrict__ fmsg,
                       const int*  nstart_p,
                       const float* __restrict__ enc_w,
                       const float* __restrict__ enc_b,
                       const float* __restrict__ act_w)
{
    int n = blockIdx.x, t = threadIdx.x;
    int lane = t & 31;
    __shared__ float sx[INF_];
    __shared__ float sw[4];
    if (t < INF_) sx[t] = xa[n * INF_ + t];
    __syncthreads();

    float acc = enc_b[t];
#pragma unroll
    for (int k = 0; k < INF_; k++) acc += sx[k] * enc_w[k * Hh + t];

    g_feats[n * Hh + t] = acc;
    g_final[n * Hh + t] = 0.0f;

    float pa = acc * act_w[t];
#pragma unroll
    for (int o = 16; o; o >>= 1) pa += __shfl_xor_sync(0xffffffffu, pa, o);
    if (lane == 0) sw[t >> 5] = pa;
    __syncthreads();
    if (t == 0) g_actf[n] = sw[0] + sw[1] + sw[2] + sw[3];

    int ns = nstart_p ? *nstart_p : NSMAX;
    if (n < ns) g_msgs[(size_t)n * Mm + t] = fmsg[n * Mm + t];
}

// ---------------------------------------------------------------------------
// Kernel 2: sequential queue simulation. ONE block, 512 threads (16 warps).
//  Batched steps (B<=2): consecutive processable same-mid DISTINCT-node
//  entries are exactly commutable (disjoint node state, shared msg partials,
//  enqueue order preserved). B=2 keeps register demand under the 128-reg
//  ceiling (R8's B=4 spilled).
//  * queue + tact + actf caches in SMEM; msg-half weights in SMEM
//  * hit-path weights register-resident (fma.rn.f32x2), 2 interleaved rows
//  * s_wtmp double-buffered (parity); lazy actf commit with in-reg subst
// ---------------------------------------------------------------------------
__global__ void __launch_bounds__(512, 1) k_main(
    const int*  __restrict__ neighbors,
    const int*  nstart_p,
    const float* __restrict__ ns_w, const float* __restrict__ ns_b,
    const float* __restrict__ nm_w, const float* __restrict__ nm_b,
    const float* __restrict__ act_w, const float* __restrict__ act_b)
{
    extern __shared__ __align__(16) float dyn[];
    float* s_mwA  = dyn;                      // ns_w rows 128..255 (64 KB)
    float* s_mwB  = dyn + 128 * 128;          // nm_w rows 128..255 (64 KB)
    int*   s_qpack = (int*)(dyn + 2 * 128 * 128);   // packed queue (40 KB)

    __shared__ float s_tact[Nn];                    // 4 KB
    __shared__ float s_actf[Nn];                    // 4 KB
    __shared__ __align__(16) float xs[2][128];      // feats rows (batch)
    __shared__ __align__(16) float ys[2][128];      // ns outputs (batch)
    __shared__ __align__(16) float s_fin[2][128];   // final rows (batch)
    __shared__ float s_msg[128];
    __shared__ float s_nsmsg[128], s_nmmsg[128];    // cached msg-half partials
    __shared__ __align__(16) float sredA[8 * 128];
    __shared__ __align__(16) float sredB[8 * 128];
    __shared__ float s_actw[256];
    __shared__ float s_nsb[128], s_nmb[128];
    __shared__ __align__(16) float s_wtmp[2][2][16];  // actf partials, dbl-buffered
    __shared__ float s_wactm[4];
    __shared__ float s_actmsg;

    const int t    = threadIdx.x;
    const int lane = t & 31;
    const int warp = t >> 5;
    const unsigned FULL = 0xffffffffu;

    if (t < 256) s_actw[t] = act_w[t];
    if (t < 128) { s_nsb[t] = ns_b[t]; s_nmb[t] = nm_b[t]; }
    if (t < 64)  ((float*)s_wtmp)[t] = 0.0f;
    if (t == 0)  s_actmsg = 0.0f;
    const float actb = act_b[0];

    for (int i = t; i < Nn; i += 512) { s_tact[i] = 0.0f; s_actf[i] = g_actf[i]; }

    const int ns0 = nstart_p ? *nstart_p : NSMAX;
    for (int i = t; i < ns0; i += 512) s_qpack[i] = (i << 10) | i;  // mid=i,node=i

    // msg-half weights into SMEM (rows 128..255 of both matrices)
    {
        const float4* a4 = (const float4*)(ns_w + 128 * Hh);
        const float4* b4 = (const float4*)(nm_w + 128 * Hh);
        for (int i = t; i < 128 * 32; i += 512) {
            ((float4*)s_mwA)[i] = a4[i];
            ((float4*)s_mwB)[i] = b4[i];
        }
    }

    // hit-path weights into registers (k-pair packed)
    const int o = (warp << 3) + (lane & 7);     // output column owned
    const int c = lane >> 3;                    // k-chunk (0..3)
    unsigned long long wA[16], wB[16];
#pragma unroll
    for (int kk = 0; kk < 16; kk++) {
        int k = c * 32 + 2 * kk;
        wA[kk] = pack2(ns_w[k * Hh + o], ns_w[(k + 1) * Hh + o]);
        wB[kk] = pack2(nm_w[k * Hh + o], nm_w[(k + 1) * Hh + o]);
    }

    int head = 0, tail = ns0, nproc = 0, last_mid = -1;
    int Bp = 0;                                     // prev batch size
    int pn0 = -1, pn1 = -1;                         // prev batch nodes
    int pp = 0;                                     // s_wtmp read-parity
    __syncthreads();

    while (true) {
        const int limit = (tail < MAXD) ? tail : MAXD;
        if (head >= limit) break;

        // ---- scan + batch build (all warps redundantly; B<=2) ----
        int alive = 0, bsz = 0, bmid = -1, lastpos = 0;
        int b0n = 0, b1n = 0;
        float b0t = 0.f, b1t = 0.f;
        {
            int p = head;
            while (true) {
                int q = p + lane;
                bool valid = q < limit;
                int pk = valid ? s_qpack[q] : 0;
                int nd = pk & 1023;
                float tv = valid ? s_tact[nd] : 2.0f;
                unsigned rem = __ballot_sync(FULL, valid && (tv <= THR));
                if (rem) {
                    int f = __ffs((int)rem) - 1; rem &= rem - 1;
                    b0n  = __shfl_sync(FULL, nd, f);
                    bmid = __shfl_sync(FULL, pk, f) >> 10;
                    b0t  = __shfl_sync(FULL, tv, f);
                    lastpos = p + f; bsz = 1; alive = 1;
                    if (rem) {
                        f = __ffs((int)rem) - 1;
                        int   fn  = __shfl_sync(FULL, nd, f);
                        int   fm  = __shfl_sync(FULL, pk, f) >> 10;
                        float ftv = __shfl_sync(FULL, tv, f);
                        if (fm == bmid && fn != b0n) {
                            b1n = fn; b1t = ftv; lastpos = p + f; bsz = 2;
                        }
                    }
                    break;
                }
                if (__ballot_sync(FULL, valid) != FULL) break;  // exhausted
                p += 32;
            }
        }
        if (!alive) break;            // all remaining dequeues are no-ops

        // ---- miss path: msg-half partials for this mid ----
        if (bmid != last_mid) {
            float mv = 0.0f;
            if (t < 128) {
                mv = g_msgs[(size_t)bmid * Mm + t];
                s_msg[t] = mv;
            }
            if (warp < 4) {
                float pa = mv * s_actw[128 + t];
#pragma unroll
                for (int oo = 16; oo; oo >>= 1)
                    pa += __shfl_xor_sync(FULL, pa, oo);
                if (lane == 0) s_wactm[warp] = pa;
            }
            __syncthreads();
            {
                const float4* w4p = (warp < 8) ? (const float4*)s_mwA
                                               : (const float4*)s_mwB;
                float* red = (warp < 8) ? sredA : sredB;
                int wl = warp & 7, kb = (warp & 7) * 16;
                float4 a = make_float4(0.f, 0.f, 0.f, 0.f);
#pragma unroll 8
                for (int kk = 0; kk < 16; kk++) {
                    float  mk = s_msg[kb + kk];
                    float4 w4 = w4p[(kb + kk) * 32 + lane];
                    a.x += mk * w4.x; a.y += mk * w4.y;
                    a.z += mk * w4.z; a.w += mk * w4.w;
                }
                ((float4*)red)[wl * 32 + lane] = a;
            }
            __syncthreads();
            if (t < 128) {
                float sa = 0.f, sb = 0.f;
#pragma unroll
                for (int j = 0; j < 8; j++) {
                    sa += sredA[j * 128 + t];
                    sb += sredB[j * 128 + t];
                }
                s_nsmsg[t] = sa; s_nmmsg[t] = sb;
            }
            if (t == 0)
                s_actmsg = s_wactm[0] + s_wactm[1] + s_wactm[2] + s_wactm[3];
            __syncthreads();
            last_mid = bmid;
        }

        // ---- gate (all threads redundantly) ----
        float ws0, ws1;
        {
            const float4* w4 = (const float4*)&s_wtmp[pp][0][0];
            float4 a = w4[0], b = w4[1], cc = w4[2], d = w4[3];
            ws0 = ((a.x + a.y) + (a.z + a.w)) + ((b.x + b.y) + (b.z + b.w));
            ws1 = ((cc.x + cc.y) + (cc.z + cc.w)) + ((d.x + d.y) + (d.z + d.w));
            // layout: s_wtmp[pp][0][0..15] = w4[0..3], s_wtmp[pp][1][0..15] = w4[4..7]
            float4 e = w4[4], f = w4[5], g = w4[6], h = w4[7];
            ws0 += 0.0f;   // (ws0 complete: rows 0 partials are w4[0..3])
            ws1 = ((e.x + e.y) + (e.z + e.w)) + ((f.x + f.y) + (f.z + f.w))
                + ((g.x + g.y) + (g.z + g.w)) + ((h.x + h.y) + (h.z + h.w));
            // recompute ws0 correctly over w4[0..3]:
            ws0 = ((a.x + a.y) + (a.z + a.w)) + ((b.x + b.y) + (b.z + b.w))
                + ((cc.x + cc.y) + (cc.z + cc.w)) + ((d.x + d.y) + (d.z + d.w));
        }
        if (t == 0 && Bp > 0) s_actf[pn0] = ws0;
        if (t == 1 && Bp > 1) s_actf[pn1] = ws1;

        float na0, na1;
        {
            float af0 = s_actf[b0n];
            if (Bp > 0 && b0n == pn0) af0 = ws0;
            if (Bp > 1 && b0n == pn1) af0 = ws1;
            float a0 = af0 + s_actmsg + actb;
            float cand0 = 1.0f / (1.0f + expf(-a0));
            na0 = (b0t + cand0 > 1.0f) ? (1.0f - b0t) : cand0;

            float af1 = s_actf[b1n];
            if (Bp > 0 && b1n == pn0) af1 = ws0;
            if (Bp > 1 && b1n == pn1) af1 = ws1;
            float a1 = af1 + s_actmsg + actb;
            float cand1 = 1.0f / (1.0f + expf(-a1));
            na1 = (b1t + cand1 > 1.0f) ? (1.0f - b1t) : cand1;
        }
        if (t == 0)           s_tact[b0n] = b0t + na0;
        if (t == 1 && bsz > 1) s_tact[b1n] = b1t + na1;

        // ---- prefetch rows + neighbors ----
        int mynb = 0;
        if (t < 128) {
            xs[0][t]    = g_feats[b0n * Hh + t];
            s_fin[0][t] = g_final[b0n * Hh + t];
            if (bsz > 1) {
                xs[1][t]    = g_feats[b1n * Hh + t];
                s_fin[1][t] = g_final[b1n * Hh + t];
            }
        } else if (warp == 4 || warp == 5) {
            int j = warp - 4;
            if (j < bsz && lane < DEGk)
                mynb = neighbors[((j == 0) ? b0n : b1n) * DEGk + lane];
        }
        __syncthreads();   // sync1: xs/s_fin/tact/actf visible

        // ---- phase 2: ns matmul (register weights, 2 interleaved rows) ----
        {
            unsigned long long a00 = 0ull, a01 = 0ull, a10 = 0ull, a11 = 0ull;
#pragma unroll
            for (int kk = 0; kk < 8; kk++) {
                const ulonglong2 x0 = ((const ulonglong2*)xs[0])[c * 8 + kk];
                const ulonglong2 x1 = ((const ulonglong2*)xs[1])[c * 8 + kk];
                a00 = fma2(x0.x, wA[2 * kk],     a00);
                a01 = fma2(x0.y, wA[2 * kk + 1], a01);
                a10 = fma2(x1.x, wA[2 * kk],     a10);
                a11 = fma2(x1.y, wA[2 * kk + 1], a11);
            }
            float r0x, r0y, u, v;
            unpack2(a00, r0x, r0y); unpack2(a01, u, v);
            r0x += u; r0y += v;
            float r1x, r1y;
            unpack2(a10, r1x, r1y); unpack2(a11, u, v);
            r1x += u; r1y += v;
            r0x += __shfl_xor_sync(FULL, r0x, 8);
            r0y += __shfl_xor_sync(FULL, r0y, 8);
            r1x += __shfl_xor_sync(FULL, r1x, 8);
            r1y += __shfl_xor_sync(FULL, r1y, 8);
            r0x += __shfl_xor_sync(FULL, r0x, 16);
            r0y += __shfl_xor_sync(FULL, r0y, 16);
            r1x += __shfl_xor_sync(FULL, r1x, 16);
            r1y += __shfl_xor_sync(FULL, r1y, 16);
            if (c == 0) {
                float s0 = r0x + r0y + s_nsb[o] + s_nsmsg[o];
                float nsv0 = fmaxf(s0, 0.0f);
                ys[0][o] = nsv0;
                g_feats[b0n * Hh + o] = nsv0;
                g_final[b0n * Hh + o] = s_fin[0][o] + nsv0 * na0;
                float s1 = r1x + r1y + s_nsb[o] + s_nsmsg[o];
                float nsv1 = fmaxf(s1, 0.0f);
                ys[1][o] = nsv1;
                if (bsz > 1) {
                    g_feats[b1n * Hh + o] = nsv1;
                    g_final[b1n * Hh + o] = s_fin[1][o] + nsv1 * na1;
                }
                float pw0 = nsv0 * s_actw[o];
                pw0 += __shfl_xor_sync(0x000000ffu, pw0, 4);
                pw0 += __shfl_xor_sync(0x000000ffu, pw0, 2);
                pw0 += __shfl_xor_sync(0x000000ffu, pw0, 1);
                float pw1 = nsv1 * s_actw[o];
                pw1 += __shfl_xor_sync(0x000000ffu, pw1, 4);
                pw1 += __shfl_xor_sync(0x000000ffu, pw1, 2);
                pw1 += __shfl_xor_sync(0x000000ffu, pw1, 1);
                if (lane == 0) {
                    s_wtmp[pp ^ 1][0][warp] = pw0;
                    s_wtmp[pp ^ 1][1][warp] = pw1;
                }
            }
        }
        __syncthreads();   // sync2: ys ready

        // ---- phase 3: nm matmul + msg stores + enqueue ----
        {
            unsigned long long a00 = 0ull, a01 = 0ull, a10 = 0ull, a11 = 0ull;
#pragma unroll
            for (int kk = 0; kk < 8; kk++) {
                const ulonglong2 y0 = ((const ulonglong2*)ys[0])[c * 8 + kk];
                const ulonglong2 y1 = ((const ulonglong2*)ys[1])[c * 8 + kk];
                a00 = fma2(y0.x, wB[2 * kk],     a00);
                a01 = fma2(y0.y, wB[2 * kk + 1], a01);
                a10 = fma2(y1.x, wB[2 * kk],     a10);
                a11 = fma2(y1.y, wB[2 * kk + 1], a11);
            }
            float r0x, r0y, u, v;
            unpack2(a00, r0x, r0y); unpack2(a01, u, v);
            r0x += u; r0y += v;
            float r1x, r1y;
            unpack2(a10, r1x, r1y); unpack2(a11, u, v);
            r1x += u; r1y += v;
            r0x += __shfl_xor_sync(FULL, r0x, 8);
            r0y += __shfl_xor_sync(FULL, r0y, 8);
            r1x += __shfl_xor_sync(FULL, r1x, 8);
            r1y += __shfl_xor_sync(FULL, r1y, 8);
            r0x += __shfl_xor_sync(FULL, r0x, 16);
            r0y += __shfl_xor_sync(FULL, r0y, 16);
            r1x += __shfl_xor_sync(FULL, r1x, 16);
            r1y += __shfl_xor_sync(FULL, r1y, 16);
            if (c == 0) {
                float s0 = r0x + r0y + s_nmb[o] + s_nmmsg[o];
                g_msgs[(size_t)(NSMAX + nproc) * Mm + o] = s0;
                if (bsz > 1) {
                    float s1 = r1x + r1y + s_nmb[o] + s_nmmsg[o];
                    g_msgs[(size_t)(NSMAX + nproc + 1) * Mm + o] = s1;
                }
            }
        }
        if (warp == 4 || warp == 5) {                  // enqueue 16 per row
            int j = warp - 4;
            if (j < bsz && lane < DEGk) {
                int slot = tail + j * DEGk + lane;
                if (slot < MAXD)
                    s_qpack[slot] = ((NSMAX + nproc + j) << 10) | mynb;
            }
        }

        // ---- commit batch state ----
        pn0 = b0n; pn1 = b1n;
        Bp = bsz;
        head = lastpos + 1;
        tail += DEGk * bsz;
        nproc += bsz;
        pp ^= 1;
        __syncthreads();   // sync3: queue/msgs visible for next scan
    }
}

// ---------------------------------------------------------------------------
// Kernel 3: readout.  g = sum_n final; logits = g . dec_w + dec_b; log_softmax
// ---------------------------------------------------------------------------
__global__ void k_readout(const float* __restrict__ dec_w,
                          const float* __restrict__ dec_b,
                          float* __restrict__ out)
{
    __shared__ float sg[Hh];
    __shared__ float sl[Pp * OUTn];
    int t = threadIdx.x;

    float acc = 0.0f;
#pragma unroll 4
    for (int n = 0; n < Nn; n++) acc += g_final[n * Hh + t];
    sg[t] = acc;
    __syncthreads();

    if (t < Pp * OUTn) {
        int p = t / OUTn, o = t - p * OUTn;
        float a = dec_b[t];
#pragma unroll 4
        for (int h = 0; h < Hh; h++)
            a += sg[h] * dec_w[(p * Hh + h) * OUTn + o];
        sl[t] = a;
    }
    __syncthreads();

    if (t < Pp) {
        float mx = -1e30f;
        for (int o = 0; o < OUTn; o++) mx = fmaxf(mx, sl[t * OUTn + o]);
        float s = 0.0f;
        for (int o = 0; o < OUTn; o++) s += expf(sl[t * OUTn + o] - mx);
        float lse = mx + logf(s);
        for (int o = 0; o < OUTn; o++)
            out[t * OUTn + o] = sl[t * OUTn + o] - lse;
    }
}

// ---------------------------------------------------------------------------
extern "C" void kernel_launch(void* const* d_in, const int* in_sizes, int n_in,
                              void* d_out, int out_size)
{
    int off = (n_in >= 14) ? 1 : 0;
    const float* xa        = (const float*)d_in[0];
    const float* fmsg      = (const float*)d_in[1];
    const int*   neighbors = (const int*)  d_in[2];
    const int*   nstart    = off ? (const int*)d_in[3] : nullptr;
    const float* enc_w = (const float*)d_in[3 + off];
    const float* enc_b = (const float*)d_in[4 + off];
    const float* ns_w  = (const float*)d_in[5 + off];
    const float* ns_b  = (const float*)d_in[6 + off];
    const float* nm_w  = (const float*)d_in[7 + off];
    const float* nm_b  = (const float*)d_in[8 + off];
    const float* act_w = (const float*)d_in[9 + off];
    const float* act_b = (const float*)d_in[10 + off];
    const float* dec_w = (const float*)d_in[11 + off];
    const float* dec_b = (const float*)d_in[12 + off];

    // dyn smem: 128 KB msg-half weights + 40 KB packed queue
    static const size_t DYN = 2 * 128 * 128 * sizeof(float) + MAXD * sizeof(int);
    cudaFuncSetAttribute(k_main, cudaFuncAttributeMaxDynamicSharedMemorySize,
                         (int)DYN);

    k_init<<<Nn, Hh>>>(xa, fmsg, nstart, enc_w, enc_b, act_w);
    k_main<<<1, 512, DYN>>>(neighbors, nstart, ns_w, ns_b, nm_w, nm_b,
                            act_w, act_b);
    k_readout<<<1, Hh>>>(dec_w, dec_b, (float*)d_out);
}